// round 2
// baseline (speedup 1.0000x reference)
#include <cuda_runtime.h>
#include <math.h>

#define KDT   0.1f
#define KG    9.81f
#define KRHO  1028.0f

// Constant block layout (floats):
// [0:36)    Minv
// [36:72)   mTot
// [72:108)  linDamp
// [108:144) linDampFow
// [144:150) quadDamp diagonal
// [150:168) Gm (6x3, row-major):  Minv @ g == Gm @ r  where r = rot row 2
#define NC 168
__device__ float g_consts[NC];

__global__ void prep_kernel(const float* mass, const float* volume,
                            const float* cog, const float* cob,
                            const float* mTot, const float* linDamp,
                            const float* linDampFow, const float* quadDamp) {
    if (threadIdx.x != 0 || blockIdx.x != 0) return;
    for (int i = 0; i < 36; i++) {
        g_consts[36 + i]  = mTot[i];
        g_consts[72 + i]  = linDamp[i];
        g_consts[108 + i] = linDampFow[i];
    }
    for (int i = 0; i < 6; i++) g_consts[144 + i] = quadDamp[i * 6 + i];

    // Gauss-Jordan 6x6 inverse with partial pivoting
    float A[6][6], B[6][6];
    for (int i = 0; i < 6; i++)
        for (int j = 0; j < 6; j++) {
            A[i][j] = mTot[i * 6 + j];
            B[i][j] = (i == j) ? 1.0f : 0.0f;
        }
    for (int c = 0; c < 6; c++) {
        int piv = c; float best = fabsf(A[c][c]);
        for (int r = c + 1; r < 6; r++) {
            float a = fabsf(A[r][c]);
            if (a > best) { best = a; piv = r; }
        }
        if (piv != c) {
            for (int j = 0; j < 6; j++) {
                float t = A[c][j]; A[c][j] = A[piv][j]; A[piv][j] = t;
                t = B[c][j]; B[c][j] = B[piv][j]; B[piv][j] = t;
            }
        }
        float inv = 1.0f / A[c][c];
        for (int j = 0; j < 6; j++) { A[c][j] *= inv; B[c][j] *= inv; }
        for (int r = 0; r < 6; r++) {
            if (r == c) continue;
            float f = A[r][c];
            for (int j = 0; j < 6; j++) { A[r][j] -= f * A[c][j]; B[r][j] -= f * B[c][j]; }
        }
    }
    for (int i = 0; i < 6; i++)
        for (int j = 0; j < 6; j++)
            g_consts[i * 6 + j] = B[i][j];

    // Restoring-force matrix:  g(r) = Ag @ r  (r = third row of rot)
    //   fbg = fgz*r,  fbb = fbz*r,  g = -[ (fgz+fbz) r ; fgz (cog x r) + fbz (cob x r) ]
    const float fgz = -mass[0] * KG;
    const float fbz = volume[0] * KRHO * KG;
    float Ag[6][3];
    for (int i = 0; i < 6; i++)
        for (int j = 0; j < 3; j++) Ag[i][j] = 0.0f;
    Ag[0][0] = Ag[1][1] = Ag[2][2] = -(fgz + fbz);
    // skew(c) = [[0,-c2,c1],[c2,0,-c0],[-c1,c0,0]];  bottom = -(fgz*skew(cog)+fbz*skew(cob))
    const float cg0 = cog[0], cg1 = cog[1], cg2 = cog[2];
    const float cb0 = cob[0], cb1 = cob[1], cb2 = cob[2];
    Ag[3][1] = -(-fgz * cg2 - fbz * cb2);
    Ag[3][2] = -( fgz * cg1 + fbz * cb1);
    Ag[4][0] = -( fgz * cg2 + fbz * cb2);
    Ag[4][2] = -(-fgz * cg0 - fbz * cb0);
    Ag[5][0] = -(-fgz * cg1 - fbz * cb1);
    Ag[5][1] = -( fgz * cg0 + fbz * cb0);
    // Gm = Minv @ Ag
    for (int i = 0; i < 6; i++)
        for (int j = 0; j < 3; j++) {
            float acc = 0.0f;
            for (int k = 0; k < 6; k++) acc += B[i][k] * Ag[k][j];
            g_consts[150 + i * 3 + j] = acc;
        }
}

// One RK stage: given (q, v) and precomputed Uv = Minv @ u, produce pd[7], vd[6].
__device__ __forceinline__ void fossen_stage(const float* __restrict__ sc,
                                             const float q[4], const float v[6],
                                             const float Uv[6],
                                             float pd[7], float vd[6]) {
    const float qx = q[0], qy = q[1], qz = q[2], qw = q[3];

    const float r00 = 1.0f - 2.0f * (qy * qy + qz * qz);
    const float r01 = 2.0f * (qx * qy - qz * qw);
    const float r02 = 2.0f * (qx * qz + qy * qw);
    const float r10 = 2.0f * (qx * qy + qz * qw);
    const float r11 = 1.0f - 2.0f * (qx * qx + qz * qz);
    const float r12 = 2.0f * (qy * qz - qx * qw);
    const float r20 = 2.0f * (qx * qz - qy * qw);
    const float r21 = 2.0f * (qy * qz + qx * qw);
    const float r22 = 1.0f - 2.0f * (qx * qx + qy * qy);

    const float v0 = v[0], v1 = v[1], v2 = v[2];
    const float w0 = v[3], w1 = v[4], w2 = v[5];

    pd[0] = r00 * v0 + r01 * v1 + r02 * v2;
    pd[1] = r10 * v0 + r11 * v1 + r12 * v2;
    pd[2] = r20 * v0 + r21 * v1 + r22 * v2;
    pd[3] = 0.5f * (-qx * w0 - qy * w1 - qz * w2);
    pd[4] = 0.5f * ( qw * w0 - qz * w1 + qy * w2);
    pd[5] = 0.5f * ( qz * w0 + qw * w1 - qx * w2);
    pd[6] = 0.5f * (-qy * w0 + qx * w1 + qw * w2);

    // Coriolis intermediates: mvt = M[0:3,:] v, mvb = M[3:6,:] v
    float mvt[3], mvb[3];
#pragma unroll
    for (int i = 0; i < 3; i++) {
        float a = 0.0f, b = 0.0f;
#pragma unroll
        for (int j = 0; j < 6; j++) {
            a += sc[36 + i * 6 + j] * v[j];
            b += sc[36 + (i + 3) * 6 + j] * v[j];
        }
        mvt[i] = a; mvb[i] = b;
    }

    // t = linDamp@v + v_i*(lf_i . v) + quad_ii|v_i|v_i - Cv   (this is  -Cv - Dv)
    float t[6];
#pragma unroll
    for (int i = 0; i < 6; i++) {
        const float vi = v[i];
        float ld = 0.0f, lf = 0.0f;
#pragma unroll
        for (int j = 0; j < 6; j++) {
            ld += sc[72 + i * 6 + j] * v[j];
            lf += sc[108 + i * 6 + j] * v[j];
        }
        t[i] = ld + vi * lf + sc[144 + i] * fabsf(vi) * vi;
    }
    // subtract Cv
    t[0] += (mvt[1] * w2 - mvt[2] * w1);
    t[1] += (mvt[2] * w0 - mvt[0] * w2);
    t[2] += (mvt[0] * w1 - mvt[1] * w0);
    t[3] += (mvt[1] * v2 - mvt[2] * v1) + (mvb[1] * w2 - mvb[2] * w1);
    t[4] += (mvt[2] * v0 - mvt[0] * v2) + (mvb[2] * w0 - mvb[0] * w2);
    t[5] += (mvt[0] * v1 - mvt[1] * v0) + (mvb[0] * w1 - mvb[1] * w0);

    // vd = Uv + Minv @ t - Gm @ r
#pragma unroll
    for (int i = 0; i < 6; i++) {
        float acc = Uv[i];
#pragma unroll
        for (int j = 0; j < 6; j++) acc += sc[i * 6 + j] * t[j];
        acc -= sc[150 + i * 3 + 0] * r20 + sc[150 + i * 3 + 1] * r21 + sc[150 + i * 3 + 2] * r22;
        vd[i] = acc;
    }
}

__global__ __launch_bounds__(256, 2) void auv_kernel(const float* __restrict__ x,
                                                     const float* __restrict__ u,
                                                     float* __restrict__ out, int K) {
    __shared__ float sx[256 * 13];
    __shared__ float su[256 * 6];
    __shared__ float sc[NC];

    const int tid = threadIdx.x;
    const int rbase = blockIdx.x * 256;
    const int total_x = K * 13;
    const int total_u = K * 6;

    if (tid < NC) sc[tid] = g_consts[tid];

#pragma unroll
    for (int i = tid; i < 256 * 13; i += 256) {
        int g = rbase * 13 + i;
        sx[i] = (g < total_x) ? x[g] : 0.0f;
    }
#pragma unroll
    for (int i = tid; i < 256 * 6; i += 256) {
        int g = rbase * 6 + i;
        su[i] = (g < total_u) ? u[g] : 0.0f;
    }
    __syncthreads();

    const int row = rbase + tid;
    const bool active = (row < K);

    float pos[3], q[4], v[6];
    const float* mx = &sx[tid * 13];
#pragma unroll
    for (int i = 0; i < 3; i++) pos[i] = mx[i];
#pragma unroll
    for (int i = 0; i < 4; i++) q[i] = mx[3 + i];
#pragma unroll
    for (int i = 0; i < 6; i++) v[i] = mx[7 + i];

    // Uv = Minv @ u (once; u is constant across both RK stages)
    float Uv[6];
#pragma unroll
    for (int i = 0; i < 6; i++) {
        float acc = 0.0f;
#pragma unroll
        for (int j = 0; j < 6; j++) acc += sc[i * 6 + j] * su[tid * 6 + j];
        Uv[i] = acc;
    }

    float pd1[7], vd1[6], pd2[7], vd2[6];
    fossen_stage(sc, q, v, Uv, pd1, vd1);

    float q2[4], v2[6];
#pragma unroll
    for (int i = 0; i < 4; i++) q2[i] = q[i] + KDT * pd1[3 + i];
#pragma unroll
    for (int i = 0; i < 6; i++) v2[i] = v[i] + KDT * vd1[i];

    fossen_stage(sc, q2, v2, Uv, pd2, vd2);

    const float hdt = 0.5f * KDT;
    float res[13];
#pragma unroll
    for (int i = 0; i < 3; i++) res[i] = pos[i] + hdt * (pd1[i] + pd2[i]);
    float qo[4];
#pragma unroll
    for (int i = 0; i < 4; i++) qo[i] = q[i] + hdt * (pd1[3 + i] + pd2[3 + i]);
    const float qn = rsqrtf(qo[0] * qo[0] + qo[1] * qo[1] + qo[2] * qo[2] + qo[3] * qo[3]);
#pragma unroll
    for (int i = 0; i < 4; i++) res[3 + i] = qo[i] * qn;
#pragma unroll
    for (int i = 0; i < 6; i++) res[7 + i] = v[i] + hdt * (vd1[i] + vd2[i]);

    __syncthreads();  // all reads of sx done before overwrite
    float* ox = &sx[tid * 13];
    if (active) {
#pragma unroll
        for (int i = 0; i < 13; i++) ox[i] = res[i];
    }
    __syncthreads();

#pragma unroll
    for (int i = tid; i < 256 * 13; i += 256) {
        int g = rbase * 13 + i;
        if (g < total_x) out[g] = sx[i];
    }
}

extern "C" void kernel_launch(void* const* d_in, const int* in_sizes, int n_in,
                              void* d_out, int out_size) {
    const float* x          = (const float*)d_in[0];
    const float* u          = (const float*)d_in[1];
    const float* mass       = (const float*)d_in[2];
    const float* volume     = (const float*)d_in[3];
    const float* cog        = (const float*)d_in[4];
    const float* cob        = (const float*)d_in[5];
    const float* mTot       = (const float*)d_in[6];
    const float* linDamp    = (const float*)d_in[7];
    const float* linDampFow = (const float*)d_in[8];
    const float* quadDamp   = (const float*)d_in[9];

    const int K = in_sizes[0] / 13;

    prep_kernel<<<1, 1>>>(mass, volume, cog, cob, mTot, linDamp, linDampFow, quadDamp);

    const int blocks = (K + 255) / 256;
    auv_kernel<<<blocks, 256>>>(x, u, (float*)d_out, K);
}

// round 3
// speedup vs baseline: 1.4593x; 1.4593x over previous
#include <cuda_runtime.h>
#include <math.h>

#define KDT   0.1f
#define KG    9.81f
#define KRHO  1028.0f

// Constant block layout (floats):
// [0:36)    Minv
// [36:72)   mTot
// [72:108)  linDamp
// [108:144) linDampFow
// [144:150) quadDamp diagonal
// [150:168) Gm (6x3, row-major):  Minv @ g == Gm @ r  where r = rot row 2
#define NC 168
__device__   float g_consts[NC];
__constant__ float c_consts[NC];

__global__ void prep_kernel(const float* mass, const float* volume,
                            const float* cog, const float* cob,
                            const float* mTot, const float* linDamp,
                            const float* linDampFow, const float* quadDamp) {
    if (threadIdx.x != 0 || blockIdx.x != 0) return;
    for (int i = 0; i < 36; i++) {
        g_consts[36 + i]  = mTot[i];
        g_consts[72 + i]  = linDamp[i];
        g_consts[108 + i] = linDampFow[i];
    }
    for (int i = 0; i < 6; i++) g_consts[144 + i] = quadDamp[i * 6 + i];

    // Gauss-Jordan 6x6 inverse with partial pivoting
    float A[6][6], B[6][6];
    for (int i = 0; i < 6; i++)
        for (int j = 0; j < 6; j++) {
            A[i][j] = mTot[i * 6 + j];
            B[i][j] = (i == j) ? 1.0f : 0.0f;
        }
    for (int c = 0; c < 6; c++) {
        int piv = c; float best = fabsf(A[c][c]);
        for (int r = c + 1; r < 6; r++) {
            float a = fabsf(A[r][c]);
            if (a > best) { best = a; piv = r; }
        }
        if (piv != c) {
            for (int j = 0; j < 6; j++) {
                float t = A[c][j]; A[c][j] = A[piv][j]; A[piv][j] = t;
                t = B[c][j]; B[c][j] = B[piv][j]; B[piv][j] = t;
            }
        }
        float inv = 1.0f / A[c][c];
        for (int j = 0; j < 6; j++) { A[c][j] *= inv; B[c][j] *= inv; }
        for (int r = 0; r < 6; r++) {
            if (r == c) continue;
            float f = A[r][c];
            for (int j = 0; j < 6; j++) { A[r][j] -= f * A[c][j]; B[r][j] -= f * B[c][j]; }
        }
    }
    for (int i = 0; i < 6; i++)
        for (int j = 0; j < 6; j++)
            g_consts[i * 6 + j] = B[i][j];

    // Restoring-force matrix:  g(r) = Ag @ r  (r = third row of rot)
    const float fgz = -mass[0] * KG;
    const float fbz = volume[0] * KRHO * KG;
    float Ag[6][3];
    for (int i = 0; i < 6; i++)
        for (int j = 0; j < 3; j++) Ag[i][j] = 0.0f;
    Ag[0][0] = Ag[1][1] = Ag[2][2] = -(fgz + fbz);
    const float cg0 = cog[0], cg1 = cog[1], cg2 = cog[2];
    const float cb0 = cob[0], cb1 = cob[1], cb2 = cob[2];
    Ag[3][1] = -(-fgz * cg2 - fbz * cb2);
    Ag[3][2] = -( fgz * cg1 + fbz * cb1);
    Ag[4][0] = -( fgz * cg2 + fbz * cb2);
    Ag[4][2] = -(-fgz * cg0 - fbz * cb0);
    Ag[5][0] = -(-fgz * cg1 - fbz * cb1);
    Ag[5][1] = -( fgz * cg0 + fbz * cb0);
    // Gm = Minv @ Ag
    for (int i = 0; i < 6; i++)
        for (int j = 0; j < 3; j++) {
            float acc = 0.0f;
            for (int k = 0; k < 6; k++) acc += B[i][k] * Ag[k][j];
            g_consts[150 + i * 3 + j] = acc;
        }
}

// One RK stage: (q, v) + precomputed Uv = Minv @ u  ->  pd[7], vd[6].
__device__ __forceinline__ void fossen_stage(const float q[4], const float v[6],
                                             const float Uv[6],
                                             float pd[7], float vd[6]) {
    const float qx = q[0], qy = q[1], qz = q[2], qw = q[3];

    const float r00 = 1.0f - 2.0f * (qy * qy + qz * qz);
    const float r01 = 2.0f * (qx * qy - qz * qw);
    const float r02 = 2.0f * (qx * qz + qy * qw);
    const float r10 = 2.0f * (qx * qy + qz * qw);
    const float r11 = 1.0f - 2.0f * (qx * qx + qz * qz);
    const float r12 = 2.0f * (qy * qz - qx * qw);
    const float r20 = 2.0f * (qx * qz - qy * qw);
    const float r21 = 2.0f * (qy * qz + qx * qw);
    const float r22 = 1.0f - 2.0f * (qx * qx + qy * qy);

    const float v0 = v[0], v1 = v[1], v2 = v[2];
    const float w0 = v[3], w1 = v[4], w2 = v[5];

    pd[0] = r00 * v0 + r01 * v1 + r02 * v2;
    pd[1] = r10 * v0 + r11 * v1 + r12 * v2;
    pd[2] = r20 * v0 + r21 * v1 + r22 * v2;
    pd[3] = 0.5f * (-qx * w0 - qy * w1 - qz * w2);
    pd[4] = 0.5f * ( qw * w0 - qz * w1 + qy * w2);
    pd[5] = 0.5f * ( qz * w0 + qw * w1 - qx * w2);
    pd[6] = 0.5f * (-qy * w0 + qx * w1 + qw * w2);

    // Coriolis intermediates: mvt = M[0:3,:] v, mvb = M[3:6,:] v
    float mvt[3], mvb[3];
#pragma unroll
    for (int i = 0; i < 3; i++) {
        float a = 0.0f, b = 0.0f;
#pragma unroll
        for (int j = 0; j < 6; j++) {
            a += c_consts[36 + i * 6 + j] * v[j];
            b += c_consts[36 + (i + 3) * 6 + j] * v[j];
        }
        mvt[i] = a; mvb[i] = b;
    }

    // t = linDamp@v + v_i*(lf_i . v) + quad_ii|v_i|v_i  (== -Dv), then += -Cv
    float t[6];
#pragma unroll
    for (int i = 0; i < 6; i++) {
        const float vi = v[i];
        float ld = 0.0f, lf = 0.0f;
#pragma unroll
        for (int j = 0; j < 6; j++) {
            ld += c_consts[72 + i * 6 + j] * v[j];
            lf += c_consts[108 + i * 6 + j] * v[j];
        }
        t[i] = ld + vi * lf + c_consts[144 + i] * fabsf(vi) * vi;
    }
    t[0] += (mvt[1] * w2 - mvt[2] * w1);
    t[1] += (mvt[2] * w0 - mvt[0] * w2);
    t[2] += (mvt[0] * w1 - mvt[1] * w0);
    t[3] += (mvt[1] * v2 - mvt[2] * v1) + (mvb[1] * w2 - mvb[2] * w1);
    t[4] += (mvt[2] * v0 - mvt[0] * v2) + (mvb[2] * w0 - mvb[0] * w2);
    t[5] += (mvt[0] * v1 - mvt[1] * v0) + (mvb[0] * w1 - mvb[1] * w0);

    // vd = Uv + Minv @ t - Gm @ r2
#pragma unroll
    for (int i = 0; i < 6; i++) {
        float acc = Uv[i];
#pragma unroll
        for (int j = 0; j < 6; j++) acc += c_consts[i * 6 + j] * t[j];
        acc -= c_consts[150 + i * 3 + 0] * r20 + c_consts[150 + i * 3 + 1] * r21
             + c_consts[150 + i * 3 + 2] * r22;
        vd[i] = acc;
    }
}

__global__ __launch_bounds__(256) void auv_kernel(const float* __restrict__ x,
                                                  const float* __restrict__ u,
                                                  float* __restrict__ out, int K) {
    __shared__ float sx[256 * 13];
    __shared__ float su[256 * 6];

    const int tid = threadIdx.x;
    const int rbase = blockIdx.x * 256;
    const int total_x = K * 13;
    const int total_u = K * 6;
    const int remx = total_x - rbase * 13;   // elements available for this block
    const int remu = total_u - rbase * 6;

    // Vectorized coalesced staging (block bases are 16B-aligned: 256*13*4, 256*6*4)
    if (remx >= 256 * 13 && remu >= 256 * 6) {
        const float4* x4 = (const float4*)(x + (size_t)rbase * 13);
        float4* sx4 = (float4*)sx;
#pragma unroll
        for (int i = tid; i < 256 * 13 / 4; i += 256) sx4[i] = x4[i];
        const float4* u4 = (const float4*)(u + (size_t)rbase * 6);
        float4* su4 = (float4*)su;
#pragma unroll
        for (int i = tid; i < 256 * 6 / 4; i += 256) su4[i] = u4[i];
    } else {
        for (int i = tid; i < 256 * 13; i += 256)
            sx[i] = (i < remx) ? x[rbase * 13 + i] : 0.0f;
        for (int i = tid; i < 256 * 6; i += 256)
            su[i] = (i < remu) ? u[rbase * 6 + i] : 0.0f;
    }
    __syncthreads();

    const int row = rbase + tid;
    const bool active = (row < K);

    float pos[3], q[4], v[6];
    const float* mx = &sx[tid * 13];
#pragma unroll
    for (int i = 0; i < 3; i++) pos[i] = mx[i];
#pragma unroll
    for (int i = 0; i < 4; i++) q[i] = mx[3 + i];
#pragma unroll
    for (int i = 0; i < 6; i++) v[i] = mx[7 + i];

    // Uv = Minv @ u (u constant across both RK stages)
    float Uv[6];
#pragma unroll
    for (int i = 0; i < 6; i++) {
        float acc = 0.0f;
#pragma unroll
        for (int j = 0; j < 6; j++) acc += c_consts[i * 6 + j] * su[tid * 6 + j];
        Uv[i] = acc;
    }

    float pd1[7], vd1[6], pd2[7], vd2[6];
    fossen_stage(q, v, Uv, pd1, vd1);

    float q2[4], v2[6];
#pragma unroll
    for (int i = 0; i < 4; i++) q2[i] = q[i] + KDT * pd1[3 + i];
#pragma unroll
    for (int i = 0; i < 6; i++) v2[i] = v[i] + KDT * vd1[i];

    fossen_stage(q2, v2, Uv, pd2, vd2);

    const float hdt = 0.5f * KDT;
    float res[13];
#pragma unroll
    for (int i = 0; i < 3; i++) res[i] = pos[i] + hdt * (pd1[i] + pd2[i]);
    float qo[4];
#pragma unroll
    for (int i = 0; i < 4; i++) qo[i] = q[i] + hdt * (pd1[3 + i] + pd2[3 + i]);
    const float qn = rsqrtf(qo[0] * qo[0] + qo[1] * qo[1] + qo[2] * qo[2] + qo[3] * qo[3]);
#pragma unroll
    for (int i = 0; i < 4; i++) res[3 + i] = qo[i] * qn;
#pragma unroll
    for (int i = 0; i < 6; i++) res[7 + i] = v[i] + hdt * (vd1[i] + vd2[i]);

    __syncthreads();  // everyone done reading sx before overwrite
    float* ox = &sx[tid * 13];
    if (active) {
#pragma unroll
        for (int i = 0; i < 13; i++) ox[i] = res[i];
    }
    __syncthreads();

    if (remx >= 256 * 13) {
        float4* o4 = (float4*)(out + (size_t)rbase * 13);
        const float4* sx4 = (const float4*)sx;
#pragma unroll
        for (int i = tid; i < 256 * 13 / 4; i += 256) o4[i] = sx4[i];
    } else {
        for (int i = tid; i < 256 * 13; i += 256)
            if (i < remx) out[rbase * 13 + i] = sx[i];
    }
}

extern "C" void kernel_launch(void* const* d_in, const int* in_sizes, int n_in,
                              void* d_out, int out_size) {
    const float* x          = (const float*)d_in[0];
    const float* u          = (const float*)d_in[1];
    const float* mass       = (const float*)d_in[2];
    const float* volume     = (const float*)d_in[3];
    const float* cog        = (const float*)d_in[4];
    const float* cob        = (const float*)d_in[5];
    const float* mTot       = (const float*)d_in[6];
    const float* linDamp    = (const float*)d_in[7];
    const float* linDampFow = (const float*)d_in[8];
    const float* quadDamp   = (const float*)d_in[9];

    const int K = in_sizes[0] / 13;

    prep_kernel<<<1, 1>>>(mass, volume, cog, cob, mTot, linDamp, linDampFow, quadDamp);

    // Copy derived constants into __constant__ bank (device-to-device, capturable)
    void* csym = nullptr; void* gsym = nullptr;
    cudaGetSymbolAddress(&csym, c_consts);
    cudaGetSymbolAddress(&gsym, g_consts);
    cudaMemcpyAsync(csym, gsym, NC * sizeof(float), cudaMemcpyDeviceToDevice);

    const int blocks = (K + 255) / 256;
    auv_kernel<<<blocks, 256>>>(x, u, (float*)d_out, K);
}

// round 4
// speedup vs baseline: 1.8116x; 1.2415x over previous
#include <cuda_runtime.h>
#include <math.h>

#define KDT   0.1f
#define KG    9.81f
#define KRHO  1028.0f

typedef unsigned long long u64;

// Constant block layout (floats). All 6x6 matrices stored COLUMN-PAIR layout:
// entry (base + j*6 + 2p, base + j*6 + 2p + 1) = (M[2p][j], M[2p+1][j])
// i.e. column j, output-row pair p. 64-bit loads of a pair are contiguous.
// [0:36)    Minv      (col-pair)
// [36:72)   mTot      (col-pair)
// [72:108)  MiLD = Minv @ linDamp (col-pair)
// [108:144) linDampFow (col-pair)
// [144:150) quadDamp diagonal
// [150:168) negGm (6x3): -Minv@Ag, col-pair, 3 columns (j*6+2p)
// [168]     lf-nonzero flag
#define NC 172
__device__               float g_consts[NC];
__constant__ __align__(16) float c_consts[NC];

__global__ void prep_kernel(const float* mass, const float* volume,
                            const float* cog, const float* cob,
                            const float* mTot, const float* linDamp,
                            const float* linDampFow, const float* quadDamp) {
    if (threadIdx.x != 0 || blockIdx.x != 0) return;

    // Gauss-Jordan 6x6 inverse with partial pivoting
    float A[6][6], B[6][6];
    for (int i = 0; i < 6; i++)
        for (int j = 0; j < 6; j++) {
            A[i][j] = mTot[i * 6 + j];
            B[i][j] = (i == j) ? 1.0f : 0.0f;
        }
    for (int c = 0; c < 6; c++) {
        int piv = c; float best = fabsf(A[c][c]);
        for (int r = c + 1; r < 6; r++) {
            float a = fabsf(A[r][c]);
            if (a > best) { best = a; piv = r; }
        }
        if (piv != c) {
            for (int j = 0; j < 6; j++) {
                float t = A[c][j]; A[c][j] = A[piv][j]; A[piv][j] = t;
                t = B[c][j]; B[c][j] = B[piv][j]; B[piv][j] = t;
            }
        }
        float inv = 1.0f / A[c][c];
        for (int j = 0; j < 6; j++) { A[c][j] *= inv; B[c][j] *= inv; }
        for (int r = 0; r < 6; r++) {
            if (r == c) continue;
            float f = A[r][c];
            for (int j = 0; j < 6; j++) { A[r][j] -= f * A[c][j]; B[r][j] -= f * B[c][j]; }
        }
    }

    // MiLD = Minv @ linDamp
    float MiLD[6][6];
    for (int i = 0; i < 6; i++)
        for (int j = 0; j < 6; j++) {
            float acc = 0.0f;
            for (int k = 0; k < 6; k++) acc += B[i][k] * linDamp[k * 6 + j];
            MiLD[i][j] = acc;
        }

    // Column-pair stores
    for (int j = 0; j < 6; j++)
        for (int p = 0; p < 3; p++) {
            g_consts[0   + j * 6 + 2 * p]     = B[2 * p][j];
            g_consts[0   + j * 6 + 2 * p + 1] = B[2 * p + 1][j];
            g_consts[36  + j * 6 + 2 * p]     = mTot[(2 * p) * 6 + j];
            g_consts[36  + j * 6 + 2 * p + 1] = mTot[(2 * p + 1) * 6 + j];
            g_consts[72  + j * 6 + 2 * p]     = MiLD[2 * p][j];
            g_consts[72  + j * 6 + 2 * p + 1] = MiLD[2 * p + 1][j];
            g_consts[108 + j * 6 + 2 * p]     = linDampFow[(2 * p) * 6 + j];
            g_consts[108 + j * 6 + 2 * p + 1] = linDampFow[(2 * p + 1) * 6 + j];
        }
    for (int i = 0; i < 6; i++) g_consts[144 + i] = quadDamp[i * 6 + i];

    // Restoring-force matrix: g(r) = Ag @ r  (r = third row of rot)
    const float fgz = -mass[0] * KG;
    const float fbz = volume[0] * KRHO * KG;
    float Ag[6][3];
    for (int i = 0; i < 6; i++)
        for (int j = 0; j < 3; j++) Ag[i][j] = 0.0f;
    Ag[0][0] = Ag[1][1] = Ag[2][2] = -(fgz + fbz);
    const float cg0 = cog[0], cg1 = cog[1], cg2 = cog[2];
    const float cb0 = cob[0], cb1 = cob[1], cb2 = cob[2];
    Ag[3][1] = -(-fgz * cg2 - fbz * cb2);
    Ag[3][2] = -( fgz * cg1 + fbz * cb1);
    Ag[4][0] = -( fgz * cg2 + fbz * cb2);
    Ag[4][2] = -(-fgz * cg0 - fbz * cb0);
    Ag[5][0] = -(-fgz * cg1 - fbz * cb1);
    Ag[5][1] = -( fgz * cg0 + fbz * cb0);
    // negGm = -(Minv @ Ag), stored col-pair
    for (int j = 0; j < 3; j++)
        for (int p = 0; p < 3; p++) {
            float a0 = 0.0f, a1 = 0.0f;
            for (int k = 0; k < 6; k++) {
                a0 += B[2 * p][k] * Ag[k][j];
                a1 += B[2 * p + 1][k] * Ag[k][j];
            }
            g_consts[150 + j * 6 + 2 * p]     = -a0;
            g_consts[150 + j * 6 + 2 * p + 1] = -a1;
        }

    // linDampFow nonzero flag
    float nz = 0.0f;
    for (int i = 0; i < 36; i++)
        if (linDampFow[i] != 0.0f) nz = 1.0f;
    g_consts[168] = nz;
}

// ---------------- packed f32x2 helpers ----------------
__device__ __forceinline__ u64 pk2(float lo, float hi) {
    u64 r; asm("mov.b64 %0,{%1,%2};" : "=l"(r) : "f"(lo), "f"(hi)); return r;
}
__device__ __forceinline__ u64 splat2(float a) {
    u64 r; asm("mov.b64 %0,{%1,%1};" : "=l"(r) : "f"(a)); return r;
}
__device__ __forceinline__ void unpk2(u64 p, float& lo, float& hi) {
    asm("mov.b64 {%0,%1},%2;" : "=f"(lo), "=f"(hi) : "l"(p));
}
__device__ __forceinline__ u64 f2fma(u64 a, u64 b, u64 c) {
    u64 d; asm("fma.rn.f32x2 %0,%1,%2,%3;" : "=l"(d) : "l"(a), "l"(b), "l"(c)); return d;
}
__device__ __forceinline__ u64 f2mul(u64 a, u64 b) {
    u64 d; asm("mul.rn.f32x2 %0,%1,%2;" : "=l"(d) : "l"(a), "l"(b)); return d;
}
__device__ __forceinline__ u64 f2add(u64 a, u64 b) {
    u64 d; asm("add.rn.f32x2 %0,%1,%2;" : "=l"(d) : "l"(a), "l"(b)); return d;
}
// 64-bit constant fetch of column-pair (base+j*6+2p is always even)
#define C2(base, j, p) (*reinterpret_cast<const u64*>(&c_consts[(base) + (j) * 6 + (p) * 2]))

// One RK stage. q,v scalar; sv = splats of v; Uvp = packed Minv@u.
// Outputs pd[7] scalar, vdp[3] packed (pairs (0,1),(2,3),(4,5)).
__device__ __forceinline__ void fossen_stage(const float q[4], const float v[6],
                                             const u64 sv[6], const u64 Uvp[3],
                                             float pd[7], u64 vdp[3]) {
    const float qx = q[0], qy = q[1], qz = q[2], qw = q[3];

    const float r00 = 1.0f - 2.0f * (qy * qy + qz * qz);
    const float r01 = 2.0f * (qx * qy - qz * qw);
    const float r02 = 2.0f * (qx * qz + qy * qw);
    const float r10 = 2.0f * (qx * qy + qz * qw);
    const float r11 = 1.0f - 2.0f * (qx * qx + qz * qz);
    const float r12 = 2.0f * (qy * qz - qx * qw);
    const float r20 = 2.0f * (qx * qz - qy * qw);
    const float r21 = 2.0f * (qy * qz + qx * qw);
    const float r22 = 1.0f - 2.0f * (qx * qx + qy * qy);

    const float v0 = v[0], v1 = v[1], v2 = v[2];
    const float w0 = v[3], w1 = v[4], w2 = v[5];

    pd[0] = r00 * v0 + r01 * v1 + r02 * v2;
    pd[1] = r10 * v0 + r11 * v1 + r12 * v2;
    pd[2] = r20 * v0 + r21 * v1 + r22 * v2;
    pd[3] = 0.5f * (-qx * w0 - qy * w1 - qz * w2);
    pd[4] = 0.5f * ( qw * w0 - qz * w1 + qy * w2);
    pd[5] = 0.5f * ( qz * w0 + qw * w1 - qx * w2);
    pd[6] = 0.5f * (-qy * w0 + qx * w1 + qw * w2);

    // mv = mTot @ v  (packed, column-major accumulate)
    u64 mvp[3];
#pragma unroll
    for (int p = 0; p < 3; p++) mvp[p] = f2mul(C2(36, 0, p), sv[0]);
#pragma unroll
    for (int j = 1; j < 6; j++)
#pragma unroll
        for (int p = 0; p < 3; p++) mvp[p] = f2fma(C2(36, j, p), sv[j], mvp[p]);
    float mv0, mv1, mv2, mv3, mv4, mv5;
    unpk2(mvp[0], mv0, mv1); unpk2(mvp[1], mv2, mv3); unpk2(mvp[2], mv4, mv5);

    // s = quad|v|v - Cv  (scalar)
    float s[6];
    s[0] = c_consts[144] * fabsf(v0) * v0 + (mv1 * w2 - mv2 * w1);
    s[1] = c_consts[145] * fabsf(v1) * v1 + (mv2 * w0 - mv0 * w2);
    s[2] = c_consts[146] * fabsf(v2) * v2 + (mv0 * w1 - mv1 * w0);
    s[3] = c_consts[147] * fabsf(w0) * w0 + (mv1 * v2 - mv2 * v1) + (mv4 * w2 - mv5 * w1);
    s[4] = c_consts[148] * fabsf(w1) * w1 + (mv2 * v0 - mv0 * v2) + (mv5 * w0 - mv3 * w2);
    s[5] = c_consts[149] * fabsf(w2) * w2 + (mv0 * v1 - mv1 * v0) + (mv3 * w1 - mv4 * w0);

    // optional linDampFow term: s_i += v_i * (lf_i . v)
    if (c_consts[168] != 0.0f) {
        u64 dp[3];
#pragma unroll
        for (int p = 0; p < 3; p++) dp[p] = f2mul(C2(108, 0, p), sv[0]);
#pragma unroll
        for (int j = 1; j < 6; j++)
#pragma unroll
            for (int p = 0; p < 3; p++) dp[p] = f2fma(C2(108, j, p), sv[j], dp[p]);
        float d0, d1, d2, d3, d4, d5;
        unpk2(dp[0], d0, d1); unpk2(dp[1], d2, d3); unpk2(dp[2], d4, d5);
        s[0] += v0 * d0; s[1] += v1 * d1; s[2] += v2 * d2;
        s[3] += w0 * d3; s[4] += w1 * d4; s[5] += w2 * d5;
    }

    // vd = Uv + MiLD@v + Minv@s + negGm@r2   (packed)
    u64 acc[3] = { Uvp[0], Uvp[1], Uvp[2] };
#pragma unroll
    for (int j = 0; j < 6; j++) {
#pragma unroll
        for (int p = 0; p < 3; p++) acc[p] = f2fma(C2(72, j, p), sv[j], acc[p]);
    }
#pragma unroll
    for (int j = 0; j < 6; j++) {
        const u64 ssj = splat2(s[j]);
#pragma unroll
        for (int p = 0; p < 3; p++) acc[p] = f2fma(C2(0, j, p), ssj, acc[p]);
    }
    const u64 sr0 = splat2(r20), sr1 = splat2(r21), sr2 = splat2(r22);
#pragma unroll
    for (int p = 0; p < 3; p++) {
        acc[p] = f2fma(C2(150, 0, p), sr0, acc[p]);
        acc[p] = f2fma(C2(150, 1, p), sr1, acc[p]);
        acc[p] = f2fma(C2(150, 2, p), sr2, acc[p]);
    }
    vdp[0] = acc[0]; vdp[1] = acc[1]; vdp[2] = acc[2];
}

__global__ __launch_bounds__(256) void auv_kernel(const float* __restrict__ x,
                                                  const float* __restrict__ u,
                                                  float* __restrict__ out, int K) {
    __shared__ float sx[256 * 13];
    __shared__ float su[256 * 6];

    const int tid = threadIdx.x;
    const int rbase = blockIdx.x * 256;
    const int total_x = K * 13;
    const int total_u = K * 6;
    const int remx = total_x - rbase * 13;
    const int remu = total_u - rbase * 6;

    if (remx >= 256 * 13 && remu >= 256 * 6) {
        const float4* x4 = (const float4*)(x + (size_t)rbase * 13);
        float4* sx4 = (float4*)sx;
#pragma unroll
        for (int i = tid; i < 256 * 13 / 4; i += 256) sx4[i] = x4[i];
        const float4* u4 = (const float4*)(u + (size_t)rbase * 6);
        float4* su4 = (float4*)su;
#pragma unroll
        for (int i = tid; i < 256 * 6 / 4; i += 256) su4[i] = u4[i];
    } else {
        for (int i = tid; i < 256 * 13; i += 256)
            sx[i] = (i < remx) ? x[rbase * 13 + i] : 0.0f;
        for (int i = tid; i < 256 * 6; i += 256)
            su[i] = (i < remu) ? u[rbase * 6 + i] : 0.0f;
    }
    __syncthreads();

    const int row = rbase + tid;
    const bool active = (row < K);

    float q[4], v[6];
    const float* mx = &sx[tid * 13];
#pragma unroll
    for (int i = 0; i < 4; i++) q[i] = mx[3 + i];
#pragma unroll
    for (int i = 0; i < 6; i++) v[i] = mx[7 + i];

    // Uv = Minv @ u (packed)
    u64 Uvp[3];
    {
        const float* uu = &su[tid * 6];
        u64 s0 = splat2(uu[0]);
#pragma unroll
        for (int p = 0; p < 3; p++) Uvp[p] = f2mul(C2(0, 0, p), s0);
#pragma unroll
        for (int j = 1; j < 6; j++) {
            const u64 sj = splat2(uu[j]);
#pragma unroll
            for (int p = 0; p < 3; p++) Uvp[p] = f2fma(C2(0, j, p), sj, Uvp[p]);
        }
    }

    // Stage 1
    u64 sv1[6];
#pragma unroll
    for (int j = 0; j < 6; j++) sv1[j] = splat2(v[j]);
    float pd1[7]; u64 vd1p[3];
    fossen_stage(q, v, sv1, Uvp, pd1, vd1p);

    // Midpoint state
    const u64 dt2 = splat2(KDT);
    u64 vp[3] = { pk2(v[0], v[1]), pk2(v[2], v[3]), pk2(v[4], v[5]) };
    float q2[4], v2[6];
#pragma unroll
    for (int i = 0; i < 4; i++) q2[i] = q[i] + KDT * pd1[3 + i];
    {
        u64 v2p[3];
#pragma unroll
        for (int p = 0; p < 3; p++) v2p[p] = f2fma(dt2, vd1p[p], vp[p]);
        unpk2(v2p[0], v2[0], v2[1]); unpk2(v2p[1], v2[2], v2[3]); unpk2(v2p[2], v2[4], v2[5]);
    }

    // Stage 2
    u64 sv2[6];
#pragma unroll
    for (int j = 0; j < 6; j++) sv2[j] = splat2(v2[j]);
    float pd2[7]; u64 vd2p[3];
    fossen_stage(q2, v2, sv2, Uvp, pd2, vd2p);

    // Combine
    const float hdt = 0.5f * KDT;
    float res[13];
#pragma unroll
    for (int i = 0; i < 3; i++) res[i] = mx[i] + hdt * (pd1[i] + pd2[i]);
    float qo[4];
#pragma unroll
    for (int i = 0; i < 4; i++) qo[i] = q[i] + hdt * (pd1[3 + i] + pd2[3 + i]);
    const float qn = rsqrtf(qo[0] * qo[0] + qo[1] * qo[1] + qo[2] * qo[2] + qo[3] * qo[3]);
#pragma unroll
    for (int i = 0; i < 4; i++) res[3 + i] = qo[i] * qn;
    {
        const u64 h2 = splat2(hdt);
#pragma unroll
        for (int p = 0; p < 3; p++) {
            u64 rp = f2fma(h2, f2add(vd1p[p], vd2p[p]), vp[p]);
            unpk2(rp, res[7 + 2 * p], res[8 + 2 * p]);
        }
    }

    __syncthreads();  // all reads of sx done before overwrite
    float* ox = &sx[tid * 13];
    if (active) {
#pragma unroll
        for (int i = 0; i < 13; i++) ox[i] = res[i];
    }
    __syncthreads();

    if (remx >= 256 * 13) {
        float4* o4 = (float4*)(out + (size_t)rbase * 13);
        const float4* sx4 = (const float4*)sx;
#pragma unroll
        for (int i = tid; i < 256 * 13 / 4; i += 256) o4[i] = sx4[i];
    } else {
        for (int i = tid; i < 256 * 13; i += 256)
            if (i < remx) out[rbase * 13 + i] = sx[i];
    }
}

extern "C" void kernel_launch(void* const* d_in, const int* in_sizes, int n_in,
                              void* d_out, int out_size) {
    const float* x          = (const float*)d_in[0];
    const float* u          = (const float*)d_in[1];
    const float* mass       = (const float*)d_in[2];
    const float* volume     = (const float*)d_in[3];
    const float* cog        = (const float*)d_in[4];
    const float* cob        = (const float*)d_in[5];
    const float* mTot       = (const float*)d_in[6];
    const float* linDamp    = (const float*)d_in[7];
    const float* linDampFow = (const float*)d_in[8];
    const float* quadDamp   = (const float*)d_in[9];

    const int K = in_sizes[0] / 13;

    prep_kernel<<<1, 1>>>(mass, volume, cog, cob, mTot, linDamp, linDampFow, quadDamp);

    void* csym = nullptr; void* gsym = nullptr;
    cudaGetSymbolAddress(&csym, c_consts);
    cudaGetSymbolAddress(&gsym, g_consts);
    cudaMemcpyAsync(csym, gsym, NC * sizeof(float), cudaMemcpyDeviceToDevice);

    const int blocks = (K + 255) / 256;
    auv_kernel<<<blocks, 256>>>(x, u, (float*)d_out, K);
}